// round 9
// baseline (speedup 1.0000x reference)
#include <cuda_runtime.h>
#include <cstdint>

#define NBATCH 4
#define SEQ    4096
#define HID    2048
#define NE     64
#define NTOK   (NBATCH * SEQ)   // 16384
#define NSPLIT 8
#define KSPAN  (HID / NSPLIT)   // 256
#define TTILE  128              // tokens per block
#define NCHUNK (KSPAN / 32)     // 8

typedef unsigned long long ull;

__device__ float g_wt [HID * NE];             // w^T [k][e]
__device__ float g_wts[HID * NE];             // w^T pair-swapped [k][e^1]
__device__ float g_part[NSPLIT * NTOK * NE];  // split-K partial logits (32MB)
__device__ float g_ssum[NBATCH * NE];
__device__ int   g_cnt [NBATCH * NE];

__device__ __forceinline__ ull pack2(float lo, float hi) {
    ull r; asm("mov.b64 %0, {%1, %2};" : "=l"(r) : "f"(lo), "f"(hi)); return r;
}
__device__ __forceinline__ void unpack2(ull v, float &lo, float &hi) {
    asm("mov.b64 {%0, %1}, %2;" : "=f"(lo), "=f"(hi) : "l"(v));
}
__device__ __forceinline__ void fma2(ull &d, ull a, ull b) {
    asm("fma.rn.f32x2 %0, %1, %2, %0;" : "+l"(d) : "l"(a), "l"(b));
}
__device__ __forceinline__ void cp16(unsigned int s, const void* g) {
    asm volatile("cp.async.ca.shared.global [%0], [%1], 16;" :: "r"(s), "l"(g));
}
__device__ __forceinline__ void cp_commit() {
    asm volatile("cp.async.commit_group;");
}
__device__ __forceinline__ void cp_wait0() {
    asm volatile("cp.async.wait_group 0;");
}

// transpose w[E][H] -> g_wt[H][E] + pair-swapped g_wts; block(0,0) zeroes aux
__global__ void wt_kernel(const float* __restrict__ w) {
    __shared__ float tile[32][33];
    int bx = blockIdx.x, by = blockIdx.y;          // k-tile 0..63, e-tile 0..1
    int tx = threadIdx.x, ty = threadIdx.y;        // 32 x 8
    int t = ty * 32 + tx;
    if (bx == 0 && by == 0 && t < NBATCH * NE) { g_ssum[t] = 0.0f; g_cnt[t] = 0; }
    #pragma unroll
    for (int i = 0; i < 32; i += 8)
        tile[ty + i][tx] = w[(size_t)(by * 32 + ty + i) * HID + bx * 32 + tx];
    __syncthreads();
    #pragma unroll
    for (int i = 0; i < 32; i += 8) {
        float v = tile[tx][ty + i];
        int e = by * 32 + tx;
        int k = bx * 32 + ty + i;
        g_wt [(size_t)k * NE + e]       = v;
        g_wts[(size_t)k * NE + (e ^ 1)] = v;
    }
}

// Router GEMM, split-K=8, double-buffered staging.
// grid=1024, block=128. Block tile: 128 tok x 64 exp. Thread: 8 tok x 8 exp.
__global__ __launch_bounds__(128, 3)
void gate_kernel(const float* __restrict__ x) {
    __shared__ __align__(16) float xs[2][32 * 130];  // [buf][kk][tok]
    __shared__ __align__(16) float wn[2][32 * 64];   // [buf][kk][e]
    __shared__ __align__(16) float ws[2][32 * 64];   // [buf][kk][e^1]

    const int tid    = threadIdx.x;
    const int tile   = blockIdx.x >> 3;
    const int split  = blockIdx.x & 7;
    const int tok0   = tile * TTILE;
    const int kbase  = split * KSPAN;
    const int m      = tid & 15;
    const int e_base = (tid >> 4) * 8;

    // per-thread staging coordinates
    const int xtok = tid >> 3, xc = tid & 7;          // x: 8 iterations stride 16 tokens
    const int wrow = tid >> 4, wc4 = tid & 15;        // w: 4 iterations stride 8 rows

    ull acc[4][4], acd[4][4];
    #pragma unroll
    for (int q = 0; q < 4; q++)
        #pragma unroll
        for (int j = 0; j < 4; j++) { acc[q][j] = 0ull; acd[q][j] = 0ull; }

    float4 xr[8];

    // ---- prologue: stage chunk 0 into buf 0 ----
    {
        const int kb = kbase;
        #pragma unroll
        for (int it = 0; it < 8; it++)
            xr[it] = *(const float4*)(x + (size_t)(tok0 + xtok + it * 16) * HID + kb + xc * 4);
        #pragma unroll
        for (int it = 0; it < 4; it++) {
            int row = wrow + it * 8;
            unsigned int dn = (unsigned int)__cvta_generic_to_shared(&wn[0][row * 64 + wc4 * 4]);
            unsigned int ds = (unsigned int)__cvta_generic_to_shared(&ws[0][row * 64 + wc4 * 4]);
            cp16(dn, g_wt  + (size_t)(kb + row) * NE + wc4 * 4);
            cp16(ds, g_wts + (size_t)(kb + row) * NE + wc4 * 4);
        }
        cp_commit();
        #pragma unroll
        for (int it = 0; it < 8; it++) {
            int tok = xtok + it * 16;
            xs[0][(xc * 4 + 0) * 130 + tok] = xr[it].x;
            xs[0][(xc * 4 + 1) * 130 + tok] = xr[it].y;
            xs[0][(xc * 4 + 2) * 130 + tok] = xr[it].z;
            xs[0][(xc * 4 + 3) * 130 + tok] = xr[it].w;
        }
        cp_wait0();
        __syncthreads();
    }

    for (int t = 0; t < NCHUNK; t++) {
        const int cur = t & 1, nxt = cur ^ 1;

        // prefetch chunk t+1 (overlaps with compute below)
        if (t + 1 < NCHUNK) {
            const int kb = kbase + (t + 1) * 32;
            #pragma unroll
            for (int it = 0; it < 8; it++)
                xr[it] = *(const float4*)(x + (size_t)(tok0 + xtok + it * 16) * HID + kb + xc * 4);
            #pragma unroll
            for (int it = 0; it < 4; it++) {
                int row = wrow + it * 8;
                unsigned int dn = (unsigned int)__cvta_generic_to_shared(&wn[nxt][row * 64 + wc4 * 4]);
                unsigned int ds = (unsigned int)__cvta_generic_to_shared(&ws[nxt][row * 64 + wc4 * 4]);
                cp16(dn, g_wt  + (size_t)(kb + row) * NE + wc4 * 4);
                cp16(ds, g_wts + (size_t)(kb + row) * NE + wc4 * 4);
            }
            cp_commit();
        }

        // compute chunk t from buf[cur]
        const float* xsb = xs[cur];
        const float* wnb = wn[cur];
        const float* wsb = ws[cur];
        #pragma unroll 4
        for (int kk = 0; kk < 32; kk++) {
            const float* wr = wnb + kk * 64 + e_base;
            const float* sr = wsb + kk * 64 + e_base;
            const ulonglong2 Bn01 = *(const ulonglong2*)(wr);
            const ulonglong2 Bn23 = *(const ulonglong2*)(wr + 4);
            const ulonglong2 Bs01 = *(const ulonglong2*)(sr);
            const ulonglong2 Bs23 = *(const ulonglong2*)(sr + 4);
            #pragma unroll
            for (int q = 0; q < 4; q++) {
                ull A = *(const ull*)(xsb + kk * 130 + q * 32 + m * 2);
                fma2(acc[q][0], A, Bn01.x); fma2(acd[q][0], A, Bs01.x);
                fma2(acc[q][1], A, Bn01.y); fma2(acd[q][1], A, Bs01.y);
                fma2(acc[q][2], A, Bn23.x); fma2(acd[q][2], A, Bs23.x);
                fma2(acc[q][3], A, Bn23.y); fma2(acd[q][3], A, Bs23.y);
            }
        }

        // finish staging chunk t+1 into buf[nxt], single barrier per chunk
        if (t + 1 < NCHUNK) {
            #pragma unroll
            for (int it = 0; it < 8; it++) {
                int tok = xtok + it * 16;
                xs[nxt][(xc * 4 + 0) * 130 + tok] = xr[it].x;
                xs[nxt][(xc * 4 + 1) * 130 + tok] = xr[it].y;
                xs[nxt][(xc * 4 + 2) * 130 + tok] = xr[it].z;
                xs[nxt][(xc * 4 + 3) * 130 + tok] = xr[it].w;
            }
            cp_wait0();
            __syncthreads();
        }
    }

    // acc[q][j]=(L[t0][e0], L[t1][e0+1]); acd[q][j]=(L[t0][e0+1], L[t1][e0])
    float* P = g_part + (size_t)split * NTOK * NE;
    #pragma unroll
    for (int q = 0; q < 4; q++) {
        const int t0 = tok0 + q * 32 + m * 2;
        #pragma unroll
        for (int j = 0; j < 4; j++) {
            float alo, ahi, dlo, dhi;
            unpack2(acc[q][j], alo, ahi);
            unpack2(acd[q][j], dlo, dhi);
            const int e0 = e_base + 2 * j;
            *(ull*)(P + (size_t)t0 * NE + e0)       = pack2(alo, dlo);
            *(ull*)(P + (size_t)(t0 + 1) * NE + e0) = pack2(dhi, ahi);
        }
    }
}

// Fused epilogue: sum partials -> softmax -> top2 -> outputs + aux accum.
__global__ __launch_bounds__(256)
void epi_kernel(float* __restrict__ out) {
    __shared__ float ssum_s[NE];
    __shared__ int   cnt_s[NE];
    const int tid = threadIdx.x, warp = tid >> 5, lane = tid & 31;
    if (tid < NE) { ssum_s[tid] = 0.0f; cnt_s[tid] = 0; }
    __syncthreads();

    const int t = blockIdx.x * 8 + warp;

    float L0 = 0.0f, L1 = 0.0f;
    #pragma unroll
    for (int s = 0; s < NSPLIT; s++) {
        float a, b;
        unpack2(*(const ull*)(g_part + ((size_t)s * NTOK + t) * NE + 2 * lane), a, b);
        L0 += a; L1 += b;
    }

    float mx = fmaxf(L0, L1);
    #pragma unroll
    for (int o = 16; o; o >>= 1) mx = fmaxf(mx, __shfl_xor_sync(0xffffffffu, mx, o));
    float e0 = expf(L0 - mx), e1 = expf(L1 - mx);
    float z = e0 + e1;
    #pragma unroll
    for (int o = 16; o; o >>= 1) z += __shfl_xor_sync(0xffffffffu, z, o);
    float p0 = e0 / z, p1 = e1 / z;

    atomicAdd(&ssum_s[2 * lane],     p0);
    atomicAdd(&ssum_s[2 * lane + 1], p1);

    float tv1, tv2; int ti1, ti2;
    if (p0 >= p1) { tv1 = p0; ti1 = 2 * lane;     tv2 = p1; ti2 = 2 * lane + 1; }
    else          { tv1 = p1; ti1 = 2 * lane + 1; tv2 = p0; ti2 = 2 * lane;     }
    #pragma unroll
    for (int o = 16; o; o >>= 1) {
        float ov1 = __shfl_xor_sync(0xffffffffu, tv1, o);
        int   oi1 = __shfl_xor_sync(0xffffffffu, ti1, o);
        float ov2 = __shfl_xor_sync(0xffffffffu, tv2, o);
        int   oi2 = __shfl_xor_sync(0xffffffffu, ti2, o);
        bool obeats = (ov1 > tv1) || (ov1 == tv1 && oi1 < ti1);
        if (obeats) {
            float nv2; int ni2;
            bool mine2 = (tv1 > ov2) || (tv1 == ov2 && ti1 < oi2);
            if (mine2) { nv2 = tv1; ni2 = ti1; } else { nv2 = ov2; ni2 = oi2; }
            tv1 = ov1; ti1 = oi1; tv2 = nv2; ti2 = ni2;
        } else {
            bool beats2 = (ov1 > tv2) || (ov1 == tv2 && oi1 < ti2);
            if (beats2) { tv2 = ov1; ti2 = oi1; }
        }
    }

    if (lane == 0) {
        out[2 * t + 0] = (float)ti1;
        out[2 * t + 1] = (float)ti2;
        float zz = tv1 + tv2 + 1e-20f;
        out[2 * NTOK + 2 * t + 0] = tv1 / zz;
        out[2 * NTOK + 2 * t + 1] = tv2 / zz;
        atomicAdd(&cnt_s[ti1], 1);
        atomicAdd(&cnt_s[ti2], 1);
    }
    __syncthreads();

    const int b = (blockIdx.x * 8) >> 12;   // /4096 tokens per batch
    if (tid < NE) {
        atomicAdd(&g_ssum[b * NE + tid], ssum_s[tid]);
        atomicAdd(&g_cnt [b * NE + tid], cnt_s[tid]);
    }
}

__global__ void aux_kernel(float* __restrict__ out) {
    int t = threadIdx.x;  // 256 = NBATCH*NE
    float v = ((float)g_cnt[t] * ((float)NE / (float)(SEQ * 2))) *
              (g_ssum[t] / (float)SEQ);
    #pragma unroll
    for (int o = 16; o; o >>= 1) v += __shfl_xor_sync(0xffffffffu, v, o);
    __shared__ float wsum[8];
    if ((t & 31) == 0) wsum[t >> 5] = v;
    __syncthreads();
    if (t < 8) {
        float s = wsum[t];
        #pragma unroll
        for (int o = 4; o; o >>= 1) s += __shfl_xor_sync(0xffu, s, o);
        if (t == 0) out[4 * NTOK] = 0.01f * s / (float)NBATCH;
    }
}

extern "C" void kernel_launch(void* const* d_in, const int* in_sizes, int n_in,
                              void* d_out, int out_size) {
    const float* x = (const float*)d_in[0];
    const float* w = (const float*)d_in[1];
    float* out = (float*)d_out;

    wt_kernel<<<dim3(64, 2), dim3(32, 8)>>>(w);
    gate_kernel<<<NTOK / TTILE * NSPLIT, 128>>>(x);
    epi_kernel<<<NTOK / 8, 256>>>(out);
    aux_kernel<<<1, 256>>>(out);
}